// round 6
// baseline (speedup 1.0000x reference)
#include <cuda_runtime.h>
#include <math.h>

// Problem constants
#define NB   8
#define LQ   2048
#define LKV  2048
#define DIM  128
#define DV   128

// Tiling
#define BQ   64     // q rows per block
#define BK   128    // kv rows per tile
#define PAD  132    // padded row length in smem (floats), 528B -> 16B aligned rows, mild bank spread

// out layout: [ weights: NB*LQ*LKV ][ context: NB*LQ*DV ]
#define W_ELEMS ((size_t)NB * LQ * LKV)

__global__ __launch_bounds__(256, 1)
void attn_fused_kernel(const float* __restrict__ Q,
                       const float* __restrict__ K,
                       const float* __restrict__ V,
                       float* __restrict__ out)
{
    extern __shared__ float sm[];
    float* Qs  = sm;                 // [BQ][PAD]  (phase 2: reused as W tile)
    float* KVs = sm + BQ * PAD;      // [BK][PAD]  (K tile, then V tile)
    float* msm = KVs + BK * PAD;     // [BQ] running row max
    float* lsm = msm + BQ;           // [BQ] running row sum

    const int tid = threadIdx.x;
    const int tx  = tid & 15;        // 16 col-threads
    const int ty  = tid >> 4;        // 16 row-threads
    const int q0  = blockIdx.x * BQ;
    const int b   = blockIdx.y;

    const float scale = 0.08838834764831845f; // 1/sqrt(128)

    const float* Qg = Q + ((size_t)b * LQ + q0) * DIM;
    const float* Kg = K + (size_t)b * LKV * DIM;
    const float* Vg = V + (size_t)b * LKV * DIM;
    float* Wg = out + ((size_t)b * LQ + q0) * LKV;                  // weights rows for this block
    float* Cg = out + W_ELEMS + ((size_t)b * LQ + q0) * DV;         // context rows

    // ---- Load Q tile (scaled) ----
    for (int s = tid; s < BQ * (DIM / 4); s += 256) {
        int r  = s >> 5;        // /32 float4 per row
        int dv = s & 31;
        float4 v = reinterpret_cast<const float4*>(Qg + (size_t)r * DIM)[dv];
        v.x *= scale; v.y *= scale; v.z *= scale; v.w *= scale;
        reinterpret_cast<float4*>(Qs + r * PAD)[dv] = v;
    }
    if (tid < BQ) { msm[tid] = -INFINITY; lsm[tid] = 0.0f; }

    // =========================================================
    // Phase 1: S = Qs * K^T, write RAW scores to Wg, online m/l
    // =========================================================
    for (int t = 0; t < LKV; t += BK) {
        __syncthreads();
        // load K tile [BK][DIM]
        for (int s = tid; s < BK * (DIM / 4); s += 256) {
            int r  = s >> 5;
            int dv = s & 31;
            reinterpret_cast<float4*>(KVs + r * PAD)[dv] =
                reinterpret_cast<const float4*>(Kg + (size_t)(t + r) * DIM)[dv];
        }
        __syncthreads();

        float acc[4][8];
        #pragma unroll
        for (int i = 0; i < 4; i++)
            #pragma unroll
            for (int j = 0; j < 8; j++) acc[i][j] = 0.0f;

        #pragma unroll 8
        for (int d = 0; d < DIM; d += 4) {
            float4 qa[4];
            #pragma unroll
            for (int i = 0; i < 4; i++)
                qa[i] = *reinterpret_cast<const float4*>(Qs + (ty * 4 + i) * PAD + d);
            float4 kb[8];
            #pragma unroll
            for (int j = 0; j < 8; j++)
                kb[j] = *reinterpret_cast<const float4*>(KVs + (tx + 16 * j) * PAD + d);
            #pragma unroll
            for (int i = 0; i < 4; i++)
                #pragma unroll
                for (int j = 0; j < 8; j++) {
                    acc[i][j] += qa[i].x * kb[j].x;
                    acc[i][j] += qa[i].y * kb[j].y;
                    acc[i][j] += qa[i].z * kb[j].z;
                    acc[i][j] += qa[i].w * kb[j].w;
                }
        }

        // per-row online softmax stats + raw score writeback
        #pragma unroll
        for (int i = 0; i < 4; i++) {
            const int r = ty * 4 + i;
            float tmax = acc[i][0];
            #pragma unroll
            for (int j = 1; j < 8; j++) tmax = fmaxf(tmax, acc[i][j]);
            #pragma unroll
            for (int o = 8; o >= 1; o >>= 1)
                tmax = fmaxf(tmax, __shfl_xor_sync(0xffffffffu, tmax, o, 16));

            float mo = msm[r];
            float mn = fmaxf(mo, tmax);

            float ps = 0.0f;
            #pragma unroll
            for (int j = 0; j < 8; j++) ps += __expf(acc[i][j] - mn);
            #pragma unroll
            for (int o = 8; o >= 1; o >>= 1)
                ps += __shfl_xor_sync(0xffffffffu, ps, o, 16);

            if (tx == 0) {
                lsm[r] = lsm[r] * __expf(mo - mn) + ps;
                msm[r] = mn;
            }

            float* wrow = Wg + (size_t)r * LKV + t;
            #pragma unroll
            for (int j = 0; j < 8; j++) wrow[tx + 16 * j] = acc[i][j];
        }
    }

    // =========================================================
    // Phase 2: normalize weights (write final), ctx = W @ V
    // =========================================================
    float acc2[4][8];
    #pragma unroll
    for (int i = 0; i < 4; i++)
        #pragma unroll
        for (int j = 0; j < 8; j++) acc2[i][j] = 0.0f;

    for (int t = 0; t < LKV; t += BK) {
        __syncthreads();   // previous GEMM done before overwriting KVs / Qs(Wt)

        // load V tile [BK][DV] into KVs
        for (int s = tid; s < BK * (DV / 4); s += 256) {
            int r  = s >> 5;
            int dv = s & 31;
            reinterpret_cast<float4*>(KVs + r * PAD)[dv] =
                reinterpret_cast<const float4*>(Vg + (size_t)(t + r) * DIM)[dv];
        }

        // read raw scores, normalize, write final weights, stage W tile in Qs
        #pragma unroll
        for (int i = 0; i < 4; i++) {
            const int r = ty * 4 + i;
            const float mr   = msm[r];
            const float invl = 1.0f / lsm[r];
            float* wrow = Wg + (size_t)r * LKV + t;
            #pragma unroll
            for (int j = 0; j < 8; j++) {
                float sraw = wrow[tx + 16 * j];
                float w = __expf(sraw - mr) * invl;
                wrow[tx + 16 * j] = w;
                Qs[r * PAD + tx + 16 * j] = w;
            }
        }
        __syncthreads();

        // ctx[r][c] += sum_k Wt[r][k] * V[k][c]
        #pragma unroll 4
        for (int k = 0; k < BK; k++) {
            float a[4];
            #pragma unroll
            for (int i = 0; i < 4; i++) a[i] = Qs[(ty * 4 + i) * PAD + k];
            float bb[8];
            #pragma unroll
            for (int j = 0; j < 8; j++) bb[j] = KVs[k * PAD + tx + 16 * j];
            #pragma unroll
            for (int i = 0; i < 4; i++)
                #pragma unroll
                for (int j = 0; j < 8; j++) acc2[i][j] += a[i] * bb[j];
        }
    }

    // write context
    #pragma unroll
    for (int i = 0; i < 4; i++) {
        const int r = ty * 4 + i;
        #pragma unroll
        for (int j = 0; j < 8; j++)
            Cg[(size_t)r * DV + tx + 16 * j] = acc2[i][j];
    }
}

extern "C" void kernel_launch(void* const* d_in, const int* in_sizes, int n_in,
                              void* d_out, int out_size)
{
    const float* Q = (const float*)d_in[0];
    const float* K = (const float*)d_in[1];
    const float* V = (const float*)d_in[2];
    float* out = (float*)d_out;

    const int smem_bytes = (BQ * PAD + BK * PAD + 2 * BQ) * (int)sizeof(float); // 101,888 B
    cudaFuncSetAttribute(attn_fused_kernel,
                         cudaFuncAttributeMaxDynamicSharedMemorySize, smem_bytes);

    dim3 grid(LQ / BQ, NB);   // (32, 8)
    attn_fused_kernel<<<grid, 256, smem_bytes>>>(Q, K, V, out);
}

// round 13
// speedup vs baseline: 1.1853x; 1.1853x over previous
#include <cuda_runtime.h>
#include <cuda_bf16.h>
#include <stdint.h>
#include <math.h>

// ---------------- problem constants ----------------
#define NB    8
#define LQ    2048
#define LKV   2048
#define DIM   128
#define DV    128
#define BQ    128              // q rows per CTA
#define BK    64               // kv rows per tile
#define NT    (LKV / BK)       // 32 tiles
#define W_ELEMS ((size_t)NB * LQ * LKV)
#define SCALE 0.08838834764831845f

// ---------------- smem layout ----------------
#define PITCH  136             // bf16 elems per row (272B) -> conflict-free ldmatrix
#define SM_QH  0
#define SM_QL  34816           // 128*136*2
#define SM_KH  69632
#define SM_KL  87040           // 64*136*2 each
#define SM_TOTAL 104448

// ---------------- helpers ----------------
static __device__ __forceinline__ uint32_t smem_u32(const void* p) {
    uint32_t a;
    asm("{\n\t.reg .u64 t;\n\tcvta.to.shared.u64 t, %1;\n\tcvt.u32.u64 %0, t;\n\t}"
        : "=r"(a) : "l"(p));
    return a;
}
static __device__ __forceinline__ uint32_t pack2(float x, float y) {
    __nv_bfloat162 h = __floats2bfloat162_rn(x, y);
    return *(uint32_t*)&h;
}
static __device__ __forceinline__ float bhi(float x) {
    return __bfloat162float(__float2bfloat16(x));
}

// mma.sync m16n8k16 row.col f32.bf16.bf16.f32  (family-common, sm_80+)
#define MMA(D, A, B0, B1) \
    asm volatile("mma.sync.aligned.m16n8k16.row.col.f32.bf16.bf16.f32 " \
                 "{%0,%1,%2,%3},{%4,%5,%6,%7},{%8,%9},{%0,%1,%2,%3};" \
                 : "+f"((D)[0]), "+f"((D)[1]), "+f"((D)[2]), "+f"((D)[3]) \
                 : "r"((A)[0]), "r"((A)[1]), "r"((A)[2]), "r"((A)[3]), \
                   "r"(B0), "r"(B1))

#define LDM4(R, a) \
    asm volatile("ldmatrix.sync.aligned.m8n8.x4.shared.b16 {%0,%1,%2,%3},[%4];" \
                 : "=r"((R)[0]), "=r"((R)[1]), "=r"((R)[2]), "=r"((R)[3]) : "r"(a))
#define LDM4T(R, a) \
    asm volatile("ldmatrix.sync.aligned.m8n8.x4.trans.shared.b16 {%0,%1,%2,%3},[%4];" \
                 : "=r"((R)[0]), "=r"((R)[1]), "=r"((R)[2]), "=r"((R)[3]) : "r"(a))

// split 4 fp32 (row r, cols c..c+3) into hi/lo bf16 tiles
static __device__ __forceinline__ void split_store(__nv_bfloat16* H, __nv_bfloat16* L,
                                                   int r, int c, float4 v) {
    uint32_t* ph = (uint32_t*)(H + r * PITCH + c);
    uint32_t* pl = (uint32_t*)(L + r * PITCH + c);
    ph[0] = pack2(v.x, v.y);
    ph[1] = pack2(v.z, v.w);
    pl[0] = pack2(v.x - bhi(v.x), v.y - bhi(v.y));
    pl[1] = pack2(v.z - bhi(v.z), v.w - bhi(v.w));
}

__global__ __launch_bounds__(256)
void attn_tc(const float* __restrict__ Q, const float* __restrict__ K,
             const float* __restrict__ V, float* __restrict__ out)
{
    extern __shared__ char sm[];
    __nv_bfloat16* Qh = (__nv_bfloat16*)(sm + SM_QH);
    __nv_bfloat16* Ql = (__nv_bfloat16*)(sm + SM_QL);
    __nv_bfloat16* Kh = (__nv_bfloat16*)(sm + SM_KH);
    __nv_bfloat16* Kl = (__nv_bfloat16*)(sm + SM_KL);

    const int tid = threadIdx.x, wid = tid >> 5, lane = tid & 31;
    const int g = lane >> 2, t4 = lane & 3;       // mma quad coords
    const int mx = lane >> 3, r8 = lane & 7;      // ldmatrix coords
    const int q0 = blockIdx.x * BQ, b = blockIdx.y;
    const int r0 = 16 * wid + g, r1 = r0 + 8;     // rows this thread owns in frags

    const float* Qg = Q + ((size_t)b * LQ + q0) * DIM;
    const float* Kg = K + (size_t)b * LKV * DIM;
    const float* Vg = V + (size_t)b * LKV * DIM;
    float* Wg = out + ((size_t)b * LQ + q0) * LKV;
    float* Cg = out + W_ELEMS + ((size_t)b * LQ + q0) * DV;

    // ---- Q load (scaled) + hi/lo split ----
    for (int idx = tid; idx < BQ * 32; idx += 256) {
        int r = idx >> 5, c4 = idx & 31;
        float4 v = ((const float4*)(Qg + (size_t)r * DIM))[c4];
        v.x *= SCALE; v.y *= SCALE; v.z *= SCALE; v.w *= SCALE;
        split_store(Qh, Ql, r, c4 * 4, v);
    }
    __syncthreads();

    // ---- preload Q A-frags (8 k-steps, hi+lo) ----
    uint32_t qa[8][4], ql[8][4];
    {
        int arow = 16 * wid + (mx & 1) * 8 + r8;
        #pragma unroll
        for (int ks = 0; ks < 8; ks++) {
            int acol = 16 * ks + (mx >> 1) * 8;
            LDM4(qa[ks], smem_u32(Qh + arow * PITCH + acol));
            LDM4(ql[ks], smem_u32(Ql + arow * PITCH + acol));
        }
    }

    float m0 = -INFINITY, l0 = 0.f, m1 = -INFINITY, l1 = 0.f;

    // ================= PHASE 1: raw S = Q K^T, online m/l =================
    for (int t = 0; t < NT; t++) {
        __syncthreads();                                  // prev tile's mma done
        for (int idx = tid; idx < BK * 32; idx += 256) {  // K tile load + split
            int r = idx >> 5, c4 = idx & 31;
            float4 v = ((const float4*)(Kg + (size_t)(t * BK + r) * DIM))[c4];
            split_store(Kh, Kl, r, c4 * 4, v);
        }
        __syncthreads();

        float c[8][4];
        #pragma unroll
        for (int nb = 0; nb < 8; nb++) { c[nb][0] = c[nb][1] = c[nb][2] = c[nb][3] = 0.f; }

        #pragma unroll
        for (int ks = 0; ks < 8; ks++) {
            #pragma unroll
            for (int j = 0; j < 4; j++) {                 // n0 = 16*j (two n-blocks)
                uint32_t bh[4], bl[4];
                int brow = 16 * j + (mx >> 1) * 8 + r8;
                int bcol = 16 * ks + (mx & 1) * 8;
                LDM4(bh, smem_u32(Kh + brow * PITCH + bcol));
                LDM4(bl, smem_u32(Kl + brow * PITCH + bcol));
                MMA(c[2 * j],     qa[ks], bh[0], bh[1]);
                MMA(c[2 * j],     ql[ks], bh[0], bh[1]);
                MMA(c[2 * j],     qa[ks], bl[0], bl[1]);
                MMA(c[2 * j + 1], qa[ks], bh[2], bh[3]);
                MMA(c[2 * j + 1], ql[ks], bh[2], bh[3]);
                MMA(c[2 * j + 1], qa[ks], bl[2], bl[3]);
            }
        }

        // online softmax stats (rows r0, r1); quad lanes share a row
        float tm0 = -INFINITY, tm1 = -INFINITY;
        #pragma unroll
        for (int nb = 0; nb < 8; nb++) {
            tm0 = fmaxf(tm0, fmaxf(c[nb][0], c[nb][1]));
            tm1 = fmaxf(tm1, fmaxf(c[nb][2], c[nb][3]));
        }
        tm0 = fmaxf(tm0, __shfl_xor_sync(0xffffffffu, tm0, 1));
        tm0 = fmaxf(tm0, __shfl_xor_sync(0xffffffffu, tm0, 2));
        tm1 = fmaxf(tm1, __shfl_xor_sync(0xffffffffu, tm1, 1));
        tm1 = fmaxf(tm1, __shfl_xor_sync(0xffffffffu, tm1, 2));
        float mn0 = fmaxf(m0, tm0), mn1 = fmaxf(m1, tm1);
        float a0 = 0.f, a1 = 0.f;
        #pragma unroll
        for (int nb = 0; nb < 8; nb++) {
            a0 += __expf(c[nb][0] - mn0) + __expf(c[nb][1] - mn0);
            a1 += __expf(c[nb][2] - mn1) + __expf(c[nb][3] - mn1);
        }
        a0 += __shfl_xor_sync(0xffffffffu, a0, 1);
        a0 += __shfl_xor_sync(0xffffffffu, a0, 2);
        a1 += __shfl_xor_sync(0xffffffffu, a1, 1);
        a1 += __shfl_xor_sync(0xffffffffu, a1, 2);
        l0 = l0 * __expf(m0 - mn0) + a0; m0 = mn0;
        l1 = l1 * __expf(m1 - mn1) + a1; m1 = mn1;

        // write raw S (frag layout, 8B sector-coalesced)
        float* w0 = Wg + (size_t)r0 * LKV + t * BK + 2 * t4;
        float* w1 = Wg + (size_t)r1 * LKV + t * BK + 2 * t4;
        #pragma unroll
        for (int nb = 0; nb < 8; nb++) {
            *(float2*)(w0 + 8 * nb) = make_float2(c[nb][0], c[nb][1]);
            *(float2*)(w1 + 8 * nb) = make_float2(c[nb][2], c[nb][3]);
        }
    }

    const float il0 = 1.f / l0, il1 = 1.f / l1;

    // ================= PHASE 2: final W + ctx = W V =================
    float d[16][4];
    #pragma unroll
    for (int nb = 0; nb < 16; nb++) { d[nb][0] = d[nb][1] = d[nb][2] = d[nb][3] = 0.f; }

    for (int t = 0; t < NT; t++) {
        __syncthreads();                                  // prev tile's mma done
        for (int idx = tid; idx < BK * 32; idx += 256) {  // V tile load + split
            int r = idx >> 5, c4 = idx & 31;
            float4 v = ((const float4*)(Vg + (size_t)(t * BK + r) * DIM))[c4];
            split_store(Kh, Kl, r, c4 * 4, v);
        }
        __syncthreads();

        #pragma unroll
        for (int ks = 0; ks < 4; ks++) {                  // kv k-steps of 16
            int cb = t * BK + 16 * ks;
            float* w0 = Wg + (size_t)r0 * LKV + cb + 2 * t4;
            float* w1 = Wg + (size_t)r1 * LKV + cb + 2 * t4;
            float2 s00 = *(float2*)w0, s01 = *(float2*)(w0 + 8);
            float2 s10 = *(float2*)w1, s11 = *(float2*)(w1 + 8);
            s00.x = __expf(s00.x - m0) * il0;  s00.y = __expf(s00.y - m0) * il0;
            s01.x = __expf(s01.x - m0) * il0;  s01.y = __expf(s01.y - m0) * il0;
            s10.x = __expf(s10.x - m1) * il1;  s10.y = __expf(s10.y - m1) * il1;
            s11.x = __expf(s11.x - m1) * il1;  s11.y = __expf(s11.y - m1) * il1;
            *(float2*)w0 = s00; *(float2*)(w0 + 8) = s01;  // final weights
            *(float2*)w1 = s10; *(float2*)(w1 + 8) = s11;

            // rebuild A frags in-register (C-frag layout == A-frag layout)
            uint32_t ah[4], al[4];
            ah[0] = pack2(s00.x, s00.y); al[0] = pack2(s00.x - bhi(s00.x), s00.y - bhi(s00.y));
            ah[1] = pack2(s10.x, s10.y); al[1] = pack2(s10.x - bhi(s10.x), s10.y - bhi(s10.y));
            ah[2] = pack2(s01.x, s01.y); al[2] = pack2(s01.x - bhi(s01.x), s01.y - bhi(s01.y));
            ah[3] = pack2(s11.x, s11.y); al[3] = pack2(s11.x - bhi(s11.x), s11.y - bhi(s11.y));

            #pragma unroll
            for (int j = 0; j < 8; j++) {                 // n0 = 16*j (two n-blocks)
                uint32_t bh[4], bl[4];
                int brow = 16 * ks + (mx & 1) * 8 + r8;   // V row (kv index)
                int bcol = 16 * j + (mx >> 1) * 8;        // V col (d index)
                LDM4T(bh, smem_u32(Kh + brow * PITCH + bcol));
                LDM4T(bl, smem_u32(Kl + brow * PITCH + bcol));
                MMA(d[2 * j],     ah, bh[0], bh[1]);
                MMA(d[2 * j],     al, bh[0], bh[1]);
                MMA(d[2 * j],     ah, bl[0], bl[1]);
                MMA(d[2 * j + 1], ah, bh[2], bh[3]);
                MMA(d[2 * j + 1], al, bh[2], bh[3]);
                MMA(d[2 * j + 1], ah, bl[2], bl[3]);
            }
        }
    }

    // ---- write context (frag layout, 8B sector stores) ----
    float* c0p = Cg + (size_t)r0 * DV + 2 * t4;
    float* c1p = Cg + (size_t)r1 * DV + 2 * t4;
    #pragma unroll
    for (int nb = 0; nb < 16; nb++) {
        *(float2*)(c0p + 8 * nb) = make_float2(d[nb][0], d[nb][1]);
        *(float2*)(c1p + 8 * nb) = make_float2(d[nb][2], d[nb][3]);
    }
}

// ---------------- launch ----------------
extern "C" void kernel_launch(void* const* d_in, const int* in_sizes, int n_in,
                              void* d_out, int out_size)
{
    const float* Q = (const float*)d_in[0];
    const float* K = (const float*)d_in[1];
    const float* V = (const float*)d_in[2];
    float* out = (float*)d_out;

    cudaFuncSetAttribute(attn_tc, cudaFuncAttributeMaxDynamicSharedMemorySize, SM_TOTAL);
    dim3 grid(LQ / BQ, NB);   // (16, 8) = 128 CTAs
    attn_tc<<<grid, 256, SM_TOTAL>>>(Q, K, V, out);
}